// round 2
// baseline (speedup 1.0000x reference)
#include <cuda_runtime.h>
#include <math.h>

#define Bn 4
#define Cn 192
#define Hn 128
#define Wn 128
#define Ln (Hn * Wn)          // 16384
#define HEADS 8
#define CH 24                 // channels per head
#define HID 510
#define TIMED 256

// ---------------- scratch (device globals, no allocation) ----------------
__device__ float g_mod[2 * Bn * 2 * Cn];            // [branch][b][2C]
__device__ float g_y  [(size_t)Bn * Cn * Ln];       // LN/modulated + attn-out reuse
__device__ float g_x1 [(size_t)Bn * Cn * Ln];       // block-1 output (residual for block 2)
__device__ float g_bufA[(size_t)Bn * 2 * HID * Ln]; // conv1x1 outputs (max 1020 ch)
__device__ float g_bufB[(size_t)Bn * 3 * Cn * Ln];  // dwconv outputs (max 576 ch)
__device__ float g_S  [Bn * HEADS * CH * CH];       // attention logits/probs
__device__ float g_rn [Bn * 2 * Cn];                // 1/||row|| for q (0..191) and k (192..383)

// ---------------- time MLP: silu(t_emb) @ W^T + b ----------------
__global__ void time_mlp_kernel(const float* __restrict__ t_emb,
                                const float* __restrict__ aw, const float* __restrict__ ab,
                                const float* __restrict__ fw, const float* __restrict__ fb) {
    int b = blockIdx.x, branch = blockIdx.y;
    const float* w   = branch ? fw : aw;
    const float* bia = branch ? fb : ab;
    __shared__ float ts[TIMED];
    int tid = threadIdx.x;  // 384 threads
    if (tid < TIMED) {
        float t = t_emb[b * TIMED + tid];
        ts[tid] = t / (1.f + expf(-t));
    }
    __syncthreads();
    float s = 0.f;
    const float* wr = w + (size_t)tid * TIMED;
    #pragma unroll 8
    for (int i = 0; i < TIMED; i++) s += ts[i] * wr[i];
    g_mod[((size_t)branch * Bn + b) * (2 * Cn) + tid] = s + bia[tid];
}

// ---------------- fused channel-LN (unbiased, eps on std) + modulation ----------------
__global__ void ln_mod_kernel(const float* __restrict__ x, const float* __restrict__ w,
                              const float* __restrict__ bb, int branch,
                              float* __restrict__ y) {
    int b = blockIdx.y;
    int l = blockIdx.x * 256 + threadIdx.x;
    const float* xb = x + (size_t)b * Cn * Ln + l;
    float sum = 0.f, sq = 0.f;
    #pragma unroll 4
    for (int c = 0; c < Cn; c++) {
        float v = xb[(size_t)c * Ln];
        sum += v; sq += v * v;
    }
    float mean = sum * (1.f / Cn);
    float var  = fmaxf((sq - sum * mean) * (1.f / (Cn - 1)), 0.f);
    float inv  = 1.f / (sqrtf(var) + 1e-6f);
    const float* md = g_mod + ((size_t)branch * Bn + b) * (2 * Cn);
    float* yb = y + (size_t)b * Cn * Ln + l;
    #pragma unroll 4
    for (int c = 0; c < Cn; c++) {
        float v = (xb[(size_t)c * Ln] - mean) * inv * w[c] + bb[c];
        yb[(size_t)c * Ln] = v * (1.f + md[c]) + md[Cn + c];
    }
}

// ---------------- conv1x1 as SGEMM: Y[o,n] = sum_k W[o,k] X[k,n] + bias (+resid) ----------------
#define GB_M 64
#define GB_N 64
#define GB_K 16
__global__ void gemm_bias_kernel(const float* __restrict__ W, const float* __restrict__ X,
                                 const float* __restrict__ bias, const float* __restrict__ resid,
                                 float* __restrict__ Y, int O, int K) {
    const int N = Ln;
    int b  = blockIdx.z;
    const float* Xb = X + (size_t)b * K * N;
    float*       Yb = Y + (size_t)b * O * N;
    const float* Rb = resid ? resid + (size_t)b * O * N : nullptr;
    int m0 = blockIdx.y * GB_M;
    int n0 = blockIdx.x * GB_N;
    __shared__ float Ws[GB_K][GB_M + 1];
    __shared__ float Xs[GB_K][GB_N + 1];
    int tid = threadIdx.x;           // 256
    int tx = tid & 15, ty = tid >> 4;
    float acc[4][4] = {};
    int ktiles = (K + GB_K - 1) / GB_K;
    for (int kt = 0; kt < ktiles; kt++) {
        int k0 = kt * GB_K;
        #pragma unroll
        for (int i = 0; i < 4; i++) {          // load W tile (coalesced over k)
            int e = tid + i * 256;
            int kk = e & 15, mm = e >> 4;
            int o = m0 + mm, k = k0 + kk;
            Ws[kk][mm] = (o < O && k < K) ? W[(size_t)o * K + k] : 0.f;
        }
        #pragma unroll
        for (int i = 0; i < 4; i++) {          // load X tile (coalesced over n)
            int e = tid + i * 256;
            int nn = e & 63, kk = e >> 6;
            int k = k0 + kk;
            Xs[kk][nn] = (k < K) ? Xb[(size_t)k * N + n0 + nn] : 0.f;
        }
        __syncthreads();
        #pragma unroll
        for (int kk = 0; kk < GB_K; kk++) {
            float a[4], bv[4];
            #pragma unroll
            for (int i = 0; i < 4; i++) a[i]  = Ws[kk][ty * 4 + i];
            #pragma unroll
            for (int j = 0; j < 4; j++) bv[j] = Xs[kk][tx * 4 + j];
            #pragma unroll
            for (int i = 0; i < 4; i++)
                #pragma unroll
                for (int j = 0; j < 4; j++)
                    acc[i][j] += a[i] * bv[j];
        }
        __syncthreads();
    }
    #pragma unroll
    for (int i = 0; i < 4; i++) {
        int o = m0 + ty * 4 + i;
        if (o >= O) continue;
        float bvv = bias[o];
        #pragma unroll
        for (int j = 0; j < 4; j++) {
            int n = n0 + tx * 4 + j;
            float v = acc[i][j] + bvv;
            if (Rb) v += Rb[(size_t)o * N + n];
            Yb[(size_t)o * N + n] = v;
        }
    }
}

// ---------------- depthwise 3x3, SAME zero padding ----------------
__device__ __forceinline__ float dw3x3(const float* __restrict__ xc,
                                       const float* __restrict__ wc,
                                       int hh, int ww) {
    float s = 0.f;
    #pragma unroll
    for (int kh = 0; kh < 3; kh++) {
        int h2 = hh + kh - 1;
        if (h2 < 0 || h2 >= Hn) continue;
        #pragma unroll
        for (int kw = 0; kw < 3; kw++) {
            int w2 = ww + kw - 1;
            if (w2 < 0 || w2 >= Wn) continue;
            s += wc[kh * 3 + kw] * xc[h2 * Wn + w2];
        }
    }
    return s;
}

__global__ void dwconv_kernel(const float* __restrict__ x, const float* __restrict__ w,
                              const float* __restrict__ bias, float* __restrict__ y, int C) {
    int b = blockIdx.z, c = blockIdx.y;
    int l = blockIdx.x * 256 + threadIdx.x;
    int hh = l >> 7, ww = l & (Wn - 1);
    const float* xc = x + ((size_t)b * C + c) * Ln;
    float s = bias[c] + dw3x3(xc, w + c * 9, hh, ww);
    y[((size_t)b * C + c) * Ln + l] = s;
}

// GDFN: depthwise conv on both halves + gating fused (x1*x2)
__global__ void dwgate_kernel(const float* __restrict__ x, const float* __restrict__ w,
                              const float* __restrict__ bias, float* __restrict__ y) {
    int b = blockIdx.z, c = blockIdx.y;   // c < HID
    int l = blockIdx.x * 256 + threadIdx.x;
    int hh = l >> 7, ww = l & (Wn - 1);
    const float* x1c = x + ((size_t)b * (2 * HID) + c) * Ln;
    const float* x2c = x + ((size_t)b * (2 * HID) + c + HID) * Ln;
    float s1 = bias[c]       + dw3x3(x1c, w + c * 9,          hh, ww);
    float s2 = bias[c + HID] + dw3x3(x2c, w + (c + HID) * 9,  hh, ww);
    y[((size_t)b * HID + c) * Ln + l] = s1 * s2;
}

// ---------------- attention: row inverse norms for q,k ----------------
__global__ void rownorm_kernel(const float* __restrict__ qk) {
    int c = blockIdx.x;   // 0..383 (q rows then k rows)
    int b = blockIdx.y;
    const float* row = qk + ((size_t)b * 3 * Cn + c) * Ln;
    int tid = threadIdx.x;
    float s = 0.f;
    for (int i = tid; i < Ln; i += 256) { float v = row[i]; s += v * v; }
    #pragma unroll
    for (int off = 16; off; off >>= 1) s += __shfl_down_sync(0xffffffffu, s, off);
    __shared__ float red[8];
    if ((tid & 31) == 0) red[tid >> 5] = s;
    __syncthreads();
    if (tid < 8) {
        float v = red[tid];
        #pragma unroll
        for (int off = 4; off; off >>= 1) v += __shfl_down_sync(0xffu, v, off);
        if (tid == 0) g_rn[b * (2 * Cn) + c] = 1.f / fmaxf(sqrtf(v), 1e-12f);
    }
}

// ---------------- attention logits: split-L chunks, atomicAdd into 24x24 ----------------
__global__ void attn_logits_kernel(const float* __restrict__ qk) {
    int bh = blockIdx.y;  int b = bh >> 3, h = bh & 7;
    int l0 = blockIdx.x * 128;
    __shared__ float qs[CH * 129], ks[CH * 129];
    const float* qbase = qk + ((size_t)b * 3 * Cn +       h * CH) * Ln + l0;
    const float* kbase = qk + ((size_t)b * 3 * Cn + Cn +  h * CH) * Ln + l0;
    for (int i = threadIdx.x; i < CH * 128; i += 256) {
        int c = i >> 7, l = i & 127;
        qs[c * 129 + l] = qbase[(size_t)c * Ln + l];
        ks[c * 129 + l] = kbase[(size_t)c * Ln + l];
    }
    __syncthreads();
    int t = threadIdx.x;
    if (t < 144) {
        int c0 = (t / 12) * 2, d0 = (t % 12) * 2;
        float a00 = 0, a01 = 0, a10 = 0, a11 = 0;
        #pragma unroll 4
        for (int l = 0; l < 128; l++) {
            float q0 = qs[c0 * 129 + l], q1 = qs[(c0 + 1) * 129 + l];
            float k0 = ks[d0 * 129 + l], k1 = ks[(d0 + 1) * 129 + l];
            a00 += q0 * k0; a01 += q0 * k1; a10 += q1 * k0; a11 += q1 * k1;
        }
        float* S = g_S + (size_t)bh * (CH * CH);
        atomicAdd(&S[ c0      * CH + d0    ], a00);
        atomicAdd(&S[ c0      * CH + d0 + 1], a01);
        atomicAdd(&S[(c0 + 1) * CH + d0    ], a10);
        atomicAdd(&S[(c0 + 1) * CH + d0 + 1], a11);
    }
}

// ---------------- softmax over d (folds 1/norms and temperature) ----------------
__global__ void attn_softmax_kernel(const float* __restrict__ temp) {
    int bh = blockIdx.x;  int b = bh >> 3, h = bh & 7;
    int c = threadIdx.x;
    if (c >= CH) return;
    float* S = g_S + (size_t)bh * (CH * CH) + c * CH;
    float rq = g_rn[b * (2 * Cn) + h * CH + c];
    float tp = temp[h];
    float lo[CH];
    float mx = -1e30f;
    #pragma unroll
    for (int d = 0; d < CH; d++) {
        float v = S[d] * rq * g_rn[b * (2 * Cn) + Cn + h * CH + d] * tp;
        lo[d] = v; mx = fmaxf(mx, v);
    }
    float sum = 0.f;
    #pragma unroll
    for (int d = 0; d < CH; d++) { lo[d] = expf(lo[d] - mx); sum += lo[d]; }
    float inv = 1.f / sum;
    #pragma unroll
    for (int d = 0; d < CH; d++) S[d] = lo[d] * inv;
}

// ---------------- out = P @ V ----------------
__global__ void attn_apply_kernel(const float* __restrict__ qkv, float* __restrict__ y) {
    int b = blockIdx.z, h = blockIdx.y;
    int l = blockIdx.x * 128 + threadIdx.x;
    __shared__ float P[CH * CH];
    for (int i = threadIdx.x; i < CH * CH; i += 128)
        P[i] = g_S[(size_t)(b * HEADS + h) * (CH * CH) + i];
    __syncthreads();
    const float* vb = qkv + ((size_t)b * 3 * Cn + 2 * Cn + h * CH) * Ln + l;
    float acc[CH];
    #pragma unroll
    for (int c = 0; c < CH; c++) acc[c] = 0.f;
    #pragma unroll
    for (int d = 0; d < CH; d++) {
        float vv = vb[(size_t)d * Ln];
        #pragma unroll
        for (int c = 0; c < CH; c++) acc[c] += P[c * CH + d] * vv;
    }
    float* yb = y + ((size_t)b * Cn + h * CH) * Ln + l;
    #pragma unroll
    for (int c = 0; c < CH; c++) yb[(size_t)c * Ln] = acc[c];
}

// ---------------- launch ----------------
extern "C" void kernel_launch(void* const* d_in, const int* in_sizes, int n_in,
                              void* d_out, int out_size) {
    const float* x       = (const float*)d_in[0];
    const float* t_emb   = (const float*)d_in[1];
    const float* n1_w    = (const float*)d_in[2];
    const float* n1_b    = (const float*)d_in[3];
    const float* temp    = (const float*)d_in[4];
    const float* a_qkv_w = (const float*)d_in[5];
    const float* a_qkv_b = (const float*)d_in[6];
    const float* a_dw_w  = (const float*)d_in[7];
    const float* a_dw_b  = (const float*)d_in[8];
    const float* a_proj_w= (const float*)d_in[9];
    const float* a_proj_b= (const float*)d_in[10];
    const float* a_t_w   = (const float*)d_in[11];
    const float* a_t_b   = (const float*)d_in[12];
    const float* n2_w    = (const float*)d_in[13];
    const float* n2_b    = (const float*)d_in[14];
    const float* f_c1_w  = (const float*)d_in[15];
    const float* f_c1_b  = (const float*)d_in[16];
    const float* f_dw_w  = (const float*)d_in[17];
    const float* f_dw_b  = (const float*)d_in[18];
    const float* f_c2_w  = (const float*)d_in[19];
    const float* f_c2_b  = (const float*)d_in[20];
    const float* f_t_w   = (const float*)d_in[21];
    const float* f_t_b   = (const float*)d_in[22];
    float* out = (float*)d_out;

    float *p_y, *p_x1, *p_bufA, *p_bufB, *p_S;
    cudaGetSymbolAddress((void**)&p_y,    g_y);
    cudaGetSymbolAddress((void**)&p_x1,   g_x1);
    cudaGetSymbolAddress((void**)&p_bufA, g_bufA);
    cudaGetSymbolAddress((void**)&p_bufB, g_bufB);
    cudaGetSymbolAddress((void**)&p_S,    g_S);

    // ---- time modulation (both branches) ----
    time_mlp_kernel<<<dim3(Bn, 2), 2 * Cn>>>(t_emb, a_t_w, a_t_b, f_t_w, f_t_b);

    // ================= Block 1: MDTA =================
    ln_mod_kernel<<<dim3(Ln / 256, Bn), 256>>>(x, n1_w, n1_b, 0, p_y);
    gemm_bias_kernel<<<dim3(Ln / GB_N, (3 * Cn) / GB_M, Bn), 256>>>(
        a_qkv_w, p_y, a_qkv_b, nullptr, p_bufA, 3 * Cn, Cn);
    dwconv_kernel<<<dim3(Ln / 256, 3 * Cn, Bn), 256>>>(p_bufA, a_dw_w, a_dw_b, p_bufB, 3 * Cn);

    cudaMemsetAsync(p_S, 0, sizeof(float) * Bn * HEADS * CH * CH);
    rownorm_kernel<<<dim3(2 * Cn, Bn), 256>>>(p_bufB);
    attn_logits_kernel<<<dim3(Ln / 128, Bn * HEADS), 256>>>(p_bufB);
    attn_softmax_kernel<<<Bn * HEADS, 32>>>(temp);
    attn_apply_kernel<<<dim3(Ln / 128, HEADS, Bn), 128>>>(p_bufB, p_y);

    gemm_bias_kernel<<<dim3(Ln / GB_N, Cn / GB_M, Bn), 256>>>(
        a_proj_w, p_y, a_proj_b, x, p_x1, Cn, Cn);

    // ================= Block 2: GDFN =================
    ln_mod_kernel<<<dim3(Ln / 256, Bn), 256>>>(p_x1, n2_w, n2_b, 1, p_y);
    gemm_bias_kernel<<<dim3(Ln / GB_N, (2 * HID + GB_M - 1) / GB_M, Bn), 256>>>(
        f_c1_w, p_y, f_c1_b, nullptr, p_bufA, 2 * HID, Cn);
    dwgate_kernel<<<dim3(Ln / 256, HID, Bn), 256>>>(p_bufA, f_dw_w, f_dw_b, p_bufB);
    gemm_bias_kernel<<<dim3(Ln / GB_N, Cn / GB_M, Bn), 256>>>(
        f_c2_w, p_bufB, f_c2_b, p_x1, out, Cn, HID);
}

// round 3
// speedup vs baseline: 1.5969x; 1.5969x over previous
#include <cuda_runtime.h>
#include <math.h>

#define Bn 4
#define Cn 192
#define Hn 128
#define Wn 128
#define Ln (Hn * Wn)          // 16384
#define HEADS 8
#define CH 24                 // channels per head
#define HID 510
#define TIMED 256

typedef unsigned long long ull;

// ---------------- scratch (device globals, no allocation) ----------------
__device__ float g_mod[2 * Bn * 2 * Cn];            // [branch][b][2C]
__device__ float g_y  [(size_t)Bn * Cn * Ln];       // LN/modulated + attn-out reuse
__device__ float g_x1 [(size_t)Bn * Cn * Ln];       // block-1 output (residual for block 2)
__device__ float g_bufA[(size_t)Bn * 2 * HID * Ln]; // conv1x1 outputs (max 1020 ch)
__device__ float g_bufB[(size_t)Bn * 3 * Cn * Ln];  // dwconv outputs (max 576 ch)
__device__ float g_S  [Bn * HEADS * CH * CH];       // attention logits/probs
__device__ float g_rn [Bn * 2 * Cn];                // sum-of-squares for q rows, k rows

// ---------------- packed f32x2 helpers ----------------
__device__ __forceinline__ ull pack2(float lo, float hi) {
    ull r;
    asm("mov.b64 %0, {%1, %2};" : "=l"(r) : "f"(lo), "f"(hi));
    return r;
}
__device__ __forceinline__ void unpack2(ull v, float& lo, float& hi) {
    asm("mov.b64 {%0, %1}, %2;" : "=f"(lo), "=f"(hi) : "l"(v));
}
#define FFMA2(d, a, b) asm("fma.rn.f32x2 %0, %1, %2, %0;" : "+l"(d) : "l"(a), "l"(b))

// ---------------- time MLP: silu(t_emb) @ W^T + b ----------------
__global__ void time_mlp_kernel(const float* __restrict__ t_emb,
                                const float* __restrict__ aw, const float* __restrict__ ab,
                                const float* __restrict__ fw, const float* __restrict__ fb) {
    int b = blockIdx.x, branch = blockIdx.y;
    const float* w   = branch ? fw : aw;
    const float* bia = branch ? fb : ab;
    __shared__ float ts[TIMED];
    int tid = threadIdx.x;  // 384 threads
    if (tid < TIMED) {
        float t = t_emb[b * TIMED + tid];
        ts[tid] = t / (1.f + expf(-t));
    }
    __syncthreads();
    float s = 0.f;
    const float* wr = w + (size_t)tid * TIMED;
    #pragma unroll 8
    for (int i = 0; i < TIMED; i++) s += ts[i] * wr[i];
    g_mod[((size_t)branch * Bn + b) * (2 * Cn) + tid] = s + bia[tid];
}

// ---------------- fused channel-LN (unbiased, eps on std) + modulation ----------------
__global__ void ln_mod_kernel(const float* __restrict__ x, const float* __restrict__ w,
                              const float* __restrict__ bb, int branch,
                              float* __restrict__ y) {
    int b = blockIdx.y;
    int l = blockIdx.x * 256 + threadIdx.x;
    const float* xb = x + (size_t)b * Cn * Ln + l;
    float sum = 0.f, sq = 0.f;
    #pragma unroll 4
    for (int c = 0; c < Cn; c++) {
        float v = xb[(size_t)c * Ln];
        sum += v; sq += v * v;
    }
    float mean = sum * (1.f / Cn);
    float var  = fmaxf((sq - sum * mean) * (1.f / (Cn - 1)), 0.f);
    float inv  = 1.f / (sqrtf(var) + 1e-6f);
    const float* md = g_mod + ((size_t)branch * Bn + b) * (2 * Cn);
    float* yb = y + (size_t)b * Cn * Ln + l;
    #pragma unroll 4
    for (int c = 0; c < Cn; c++) {
        float v = (xb[(size_t)c * Ln] - mean) * inv * w[c] + bb[c];
        yb[(size_t)c * Ln] = v * (1.f + md[c]) + md[Cn + c];
    }
}

// ---------------- conv1x1 as GEMM with packed f32x2 FFMA ----------------
// Y[o,n] = sum_k W[o,k] X[k,n] + bias[o] (+resid).  BN=64, BK=8, 128 threads.
// Per-thread: (BM/8) m-rows as packed pairs  x  4 n-cols.
#define GB_N 64
#define GB_K 8
template<int BM>
__global__ __launch_bounds__(128)
void gemm2_kernel(const float* __restrict__ W, const float* __restrict__ X,
                  const float* __restrict__ bias, const float* __restrict__ resid,
                  float* __restrict__ Y, int O, int K) {
    constexpr int MT = BM / 8;       // m per thread
    constexpr int P  = MT / 2;       // packed pairs per thread
    constexpr int WL = (GB_K * BM) / 128;  // W elements loaded per thread per tile

    const int N = Ln;
    int b  = blockIdx.z;
    const float* Xb = X + (size_t)b * K * N;
    float*       Yb = Y + (size_t)b * O * N;
    const float* Rb = resid ? resid + (size_t)b * O * N : nullptr;
    int m0 = blockIdx.y * BM;
    int n0 = blockIdx.x * GB_N;

    __shared__ float As[2][GB_K][BM + 2];
    __shared__ float Bs[2][GB_K][GB_N];

    int tid = threadIdx.x;          // 128
    int tx = tid & 15;              // 16 n-groups of 4
    int ty = tid >> 4;              // 8 m-groups of MT

    // tile-load indices
    int xrow  = tid >> 4;           // 0..7 (k within tile)
    int xcol4 = (tid & 15) * 4;     // 0..60

    ull acc[P][4];
    #pragma unroll
    for (int p = 0; p < P; p++)
        #pragma unroll
        for (int j = 0; j < 4; j++) acc[p][j] = 0ull;

    int ktiles = (K + GB_K - 1) / GB_K;

    // ---- prologue: load tile 0 directly into smem[0] ----
    {
        int k = xrow;
        float4 xv = make_float4(0.f, 0.f, 0.f, 0.f);
        if (k < K) xv = *(const float4*)(Xb + (size_t)k * N + n0 + xcol4);
        *(float4*)&Bs[0][xrow][xcol4] = xv;
        #pragma unroll
        for (int i = 0; i < WL; i++) {
            int e = tid + i * 128;
            int kk = e & 7, mm = e >> 3;
            int o = m0 + mm;
            As[0][kk][mm] = (o < O && kk < K) ? W[(size_t)o * K + kk] : 0.f;
        }
    }
    __syncthreads();

    int cur = 0;
    for (int kt = 0; kt < ktiles; kt++) {
        // ---- prefetch next tile into registers ----
        float4 xv = make_float4(0.f, 0.f, 0.f, 0.f);
        float wreg[WL];
        bool have_next = (kt + 1 < ktiles);
        if (have_next) {
            int k1 = (kt + 1) * GB_K;
            int k = k1 + xrow;
            if (k < K) xv = *(const float4*)(Xb + (size_t)k * N + n0 + xcol4);
            #pragma unroll
            for (int i = 0; i < WL; i++) {
                int e = tid + i * 128;
                int kk = e & 7, mm = e >> 3;
                int o = m0 + mm, k2 = k1 + kk;
                wreg[i] = (o < O && k2 < K) ? W[(size_t)o * K + k2] : 0.f;
            }
        }

        // ---- compute ----
        #pragma unroll
        for (int kk = 0; kk < GB_K; kk++) {
            ull a[P];
            #pragma unroll
            for (int p = 0; p < P; p++)
                a[p] = *(const ull*)&As[cur][kk][ty * MT + 2 * p];
            float4 bq = *(const float4*)&Bs[cur][kk][tx * 4];
            ull b2[4];
            b2[0] = pack2(bq.x, bq.x);
            b2[1] = pack2(bq.y, bq.y);
            b2[2] = pack2(bq.z, bq.z);
            b2[3] = pack2(bq.w, bq.w);
            #pragma unroll
            for (int p = 0; p < P; p++)
                #pragma unroll
                for (int j = 0; j < 4; j++)
                    FFMA2(acc[p][j], a[p], b2[j]);
        }

        if (have_next) {
            int nxt = cur ^ 1;
            *(float4*)&Bs[nxt][xrow][xcol4] = xv;
            #pragma unroll
            for (int i = 0; i < WL; i++) {
                int e = tid + i * 128;
                int kk = e & 7, mm = e >> 3;
                As[nxt][kk][mm] = wreg[i];
            }
            __syncthreads();
            cur = nxt;
        }
    }

    // ---- epilogue ----
    int nb = n0 + tx * 4;
    #pragma unroll
    for (int p = 0; p < P; p++) {
        int o = m0 + ty * MT + 2 * p;   // even; O is even so pair valid together
        if (o >= O) continue;
        float lo[4], hi[4];
        #pragma unroll
        for (int j = 0; j < 4; j++) unpack2(acc[p][j], lo[j], hi[j]);
        float b0 = bias[o], b1 = bias[o + 1];
        float4 r0, r1;
        r0.x = lo[0] + b0; r0.y = lo[1] + b0; r0.z = lo[2] + b0; r0.w = lo[3] + b0;
        r1.x = hi[0] + b1; r1.y = hi[1] + b1; r1.z = hi[2] + b1; r1.w = hi[3] + b1;
        if (Rb) {
            float4 q0 = *(const float4*)(Rb + (size_t)o * N + nb);
            float4 q1 = *(const float4*)(Rb + (size_t)(o + 1) * N + nb);
            r0.x += q0.x; r0.y += q0.y; r0.z += q0.z; r0.w += q0.w;
            r1.x += q1.x; r1.y += q1.y; r1.z += q1.z; r1.w += q1.w;
        }
        *(float4*)(Yb + (size_t)o * N + nb) = r0;
        *(float4*)(Yb + (size_t)(o + 1) * N + nb) = r1;
    }
}

// ---------------- depthwise 3x3 via warp-per-row + shfl neighbors ----------------
__device__ __forceinline__ float4 conv_rows(const float* __restrict__ xc,
                                            const float* __restrict__ wc,
                                            int h, int lane, int col) {
    float4 out = make_float4(0.f, 0.f, 0.f, 0.f);
    float4 z = make_float4(0.f, 0.f, 0.f, 0.f);
    float4 vm = (h > 0)      ? *(const float4*)(xc + (size_t)(h - 1) * Wn + col) : z;
    float4 vc =                *(const float4*)(xc + (size_t)h * Wn + col);
    float4 vp = (h < Hn - 1) ? *(const float4*)(xc + (size_t)(h + 1) * Wn + col) : z;
    #pragma unroll
    for (int r = 0; r < 3; r++) {
        float4 v = (r == 0) ? vm : (r == 1) ? vc : vp;
        float wl = wc[r * 3 + 0], wm = wc[r * 3 + 1], wr = wc[r * 3 + 2];
        float lf = __shfl_up_sync(0xffffffffu, v.w, 1);
        float rt = __shfl_down_sync(0xffffffffu, v.x, 1);
        if (lane == 0)  lf = 0.f;
        if (lane == 31) rt = 0.f;
        out.x += wl * lf  + wm * v.x + wr * v.y;
        out.y += wl * v.x + wm * v.y + wr * v.z;
        out.z += wl * v.y + wm * v.z + wr * v.w;
        out.w += wl * v.z + wm * v.w + wr * rt;
    }
    return out;
}

// qkv dwconv; fuses sum-of-squares accumulation for q/k rows (c < qkC)
__global__ void dwconv2_kernel(const float* __restrict__ x, const float* __restrict__ w,
                               const float* __restrict__ bias, float* __restrict__ y,
                               int C, int qkC) {
    int b = blockIdx.z, c = blockIdx.y;
    int warp = threadIdx.x >> 5, lane = threadIdx.x & 31;
    int h = blockIdx.x * 8 + warp;
    int col = lane * 4;
    const float* xc = x + ((size_t)b * C + c) * Ln;
    float4 out = conv_rows(xc, w + c * 9, h, lane, col);
    float bv = bias[c];
    out.x += bv; out.y += bv; out.z += bv; out.w += bv;
    *(float4*)(y + ((size_t)b * C + c) * Ln + (size_t)h * Wn + col) = out;
    if (c < qkC) {
        float ss = out.x * out.x + out.y * out.y + out.z * out.z + out.w * out.w;
        #pragma unroll
        for (int off = 16; off; off >>= 1) ss += __shfl_down_sync(0xffffffffu, ss, off);
        if (lane == 0) atomicAdd(&g_rn[b * (2 * Cn) + c], ss);
    }
}

// GDFN: depthwise conv on both halves + gating fused (x1*x2)
__global__ void dwgate2_kernel(const float* __restrict__ x, const float* __restrict__ w,
                               const float* __restrict__ bias, float* __restrict__ y) {
    int b = blockIdx.z, c = blockIdx.y;   // c < HID
    int warp = threadIdx.x >> 5, lane = threadIdx.x & 31;
    int h = blockIdx.x * 8 + warp;
    int col = lane * 4;
    const float* x1c = x + ((size_t)b * (2 * HID) + c) * Ln;
    const float* x2c = x + ((size_t)b * (2 * HID) + c + HID) * Ln;
    float4 o1 = conv_rows(x1c, w + c * 9, h, lane, col);
    float4 o2 = conv_rows(x2c, w + (size_t)(c + HID) * 9, h, lane, col);
    float b1 = bias[c], b2 = bias[c + HID];
    float4 out;
    out.x = (o1.x + b1) * (o2.x + b2);
    out.y = (o1.y + b1) * (o2.y + b2);
    out.z = (o1.z + b1) * (o2.z + b2);
    out.w = (o1.w + b1) * (o2.w + b2);
    *(float4*)(y + ((size_t)b * HID + c) * Ln + (size_t)h * Wn + col) = out;
}

// ---------------- attention logits: split-L chunks, atomicAdd into 24x24 ----------------
__global__ void attn_logits_kernel(const float* __restrict__ qk) {
    int bh = blockIdx.y;  int b = bh >> 3, h = bh & 7;
    int l0 = blockIdx.x * 128;
    __shared__ float qs[CH * 129], ks[CH * 129];
    const float* qbase = qk + ((size_t)b * 3 * Cn +       h * CH) * Ln + l0;
    const float* kbase = qk + ((size_t)b * 3 * Cn + Cn +  h * CH) * Ln + l0;
    for (int i = threadIdx.x; i < CH * 128; i += 256) {
        int c = i >> 7, l = i & 127;
        qs[c * 129 + l] = qbase[(size_t)c * Ln + l];
        ks[c * 129 + l] = kbase[(size_t)c * Ln + l];
    }
    __syncthreads();
    int t = threadIdx.x;
    if (t < 144) {
        int c0 = (t / 12) * 2, d0 = (t % 12) * 2;
        float a00 = 0, a01 = 0, a10 = 0, a11 = 0;
        #pragma unroll 4
        for (int l = 0; l < 128; l++) {
            float q0 = qs[c0 * 129 + l], q1 = qs[(c0 + 1) * 129 + l];
            float k0 = ks[d0 * 129 + l], k1 = ks[(d0 + 1) * 129 + l];
            a00 += q0 * k0; a01 += q0 * k1; a10 += q1 * k0; a11 += q1 * k1;
        }
        float* S = g_S + (size_t)bh * (CH * CH);
        atomicAdd(&S[ c0      * CH + d0    ], a00);
        atomicAdd(&S[ c0      * CH + d0 + 1], a01);
        atomicAdd(&S[(c0 + 1) * CH + d0    ], a10);
        atomicAdd(&S[(c0 + 1) * CH + d0 + 1], a11);
    }
}

// ---------------- softmax over d (folds 1/norms and temperature) ----------------
__global__ void attn_softmax_kernel(const float* __restrict__ temp) {
    int bh = blockIdx.x;  int b = bh >> 3, h = bh & 7;
    int c = threadIdx.x;
    if (c >= CH) return;
    float* S = g_S + (size_t)bh * (CH * CH) + c * CH;
    float rq = 1.f / fmaxf(sqrtf(g_rn[b * (2 * Cn) + h * CH + c]), 1e-12f);
    float tp = temp[h];
    float lo[CH];
    float mx = -1e30f;
    #pragma unroll
    for (int d = 0; d < CH; d++) {
        float rk = 1.f / fmaxf(sqrtf(g_rn[b * (2 * Cn) + Cn + h * CH + d]), 1e-12f);
        float v = S[d] * rq * rk * tp;
        lo[d] = v; mx = fmaxf(mx, v);
    }
    float sum = 0.f;
    #pragma unroll
    for (int d = 0; d < CH; d++) { lo[d] = expf(lo[d] - mx); sum += lo[d]; }
    float inv = 1.f / sum;
    #pragma unroll
    for (int d = 0; d < CH; d++) S[d] = lo[d] * inv;
}

// ---------------- out = P @ V ----------------
__global__ void attn_apply_kernel(const float* __restrict__ qkv, float* __restrict__ y) {
    int b = blockIdx.z, h = blockIdx.y;
    int l = blockIdx.x * 128 + threadIdx.x;
    __shared__ float P[CH * CH];
    for (int i = threadIdx.x; i < CH * CH; i += 128)
        P[i] = g_S[(size_t)(b * HEADS + h) * (CH * CH) + i];
    __syncthreads();
    const float* vb = qkv + ((size_t)b * 3 * Cn + 2 * Cn + h * CH) * Ln + l;
    float acc[CH];
    #pragma unroll
    for (int c = 0; c < CH; c++) acc[c] = 0.f;
    #pragma unroll
    for (int d = 0; d < CH; d++) {
        float vv = vb[(size_t)d * Ln];
        #pragma unroll
        for (int c = 0; c < CH; c++) acc[c] += P[c * CH + d] * vv;
    }
    float* yb = y + ((size_t)b * Cn + h * CH) * Ln + l;
    #pragma unroll
    for (int c = 0; c < CH; c++) yb[(size_t)c * Ln] = acc[c];
}

// ---------------- launch ----------------
extern "C" void kernel_launch(void* const* d_in, const int* in_sizes, int n_in,
                              void* d_out, int out_size) {
    const float* x       = (const float*)d_in[0];
    const float* t_emb   = (const float*)d_in[1];
    const float* n1_w    = (const float*)d_in[2];
    const float* n1_b    = (const float*)d_in[3];
    const float* temp    = (const float*)d_in[4];
    const float* a_qkv_w = (const float*)d_in[5];
    const float* a_qkv_b = (const float*)d_in[6];
    const float* a_dw_w  = (const float*)d_in[7];
    const float* a_dw_b  = (const float*)d_in[8];
    const float* a_proj_w= (const float*)d_in[9];
    const float* a_proj_b= (const float*)d_in[10];
    const float* a_t_w   = (const float*)d_in[11];
    const float* a_t_b   = (const float*)d_in[12];
    const float* n2_w    = (const float*)d_in[13];
    const float* n2_b    = (const float*)d_in[14];
    const float* f_c1_w  = (const float*)d_in[15];
    const float* f_c1_b  = (const float*)d_in[16];
    const float* f_dw_w  = (const float*)d_in[17];
    const float* f_dw_b  = (const float*)d_in[18];
    const float* f_c2_w  = (const float*)d_in[19];
    const float* f_c2_b  = (const float*)d_in[20];
    const float* f_t_w   = (const float*)d_in[21];
    const float* f_t_b   = (const float*)d_in[22];
    float* out = (float*)d_out;

    float *p_y, *p_x1, *p_bufA, *p_bufB, *p_S, *p_rn;
    cudaGetSymbolAddress((void**)&p_y,    g_y);
    cudaGetSymbolAddress((void**)&p_x1,   g_x1);
    cudaGetSymbolAddress((void**)&p_bufA, g_bufA);
    cudaGetSymbolAddress((void**)&p_bufB, g_bufB);
    cudaGetSymbolAddress((void**)&p_S,    g_S);
    cudaGetSymbolAddress((void**)&p_rn,   g_rn);

    // ---- time modulation (both branches) ----
    time_mlp_kernel<<<dim3(Bn, 2), 2 * Cn>>>(t_emb, a_t_w, a_t_b, f_t_w, f_t_b);

    cudaMemsetAsync(p_S,  0, sizeof(float) * Bn * HEADS * CH * CH);
    cudaMemsetAsync(p_rn, 0, sizeof(float) * Bn * 2 * Cn);

    // ================= Block 1: MDTA =================
    ln_mod_kernel<<<dim3(Ln / 256, Bn), 256>>>(x, n1_w, n1_b, 0, p_y);
    gemm2_kernel<96><<<dim3(Ln / GB_N, 6, Bn), 128>>>(
        a_qkv_w, p_y, a_qkv_b, nullptr, p_bufA, 3 * Cn, Cn);
    dwconv2_kernel<<<dim3(Hn / 8, 3 * Cn, Bn), 256>>>(
        p_bufA, a_dw_w, a_dw_b, p_bufB, 3 * Cn, 2 * Cn);

    attn_logits_kernel<<<dim3(Ln / 128, Bn * HEADS), 256>>>(p_bufB);
    attn_softmax_kernel<<<Bn * HEADS, 32>>>(temp);
    attn_apply_kernel<<<dim3(Ln / 128, HEADS, Bn), 128>>>(p_bufB, p_y);

    gemm2_kernel<96><<<dim3(Ln / GB_N, 2, Bn), 128>>>(
        a_proj_w, p_y, a_proj_b, x, p_x1, Cn, Cn);

    // ================= Block 2: GDFN =================
    ln_mod_kernel<<<dim3(Ln / 256, Bn), 256>>>(p_x1, n2_w, n2_b, 1, p_y);
    gemm2_kernel<128><<<dim3(Ln / GB_N, 8, Bn), 128>>>(
        f_c1_w, p_y, f_c1_b, nullptr, p_bufA, 2 * HID, Cn);
    dwgate2_kernel<<<dim3(Hn / 8, HID, Bn), 256>>>(p_bufA, f_dw_w, f_dw_b, p_bufB);
    gemm2_kernel<96><<<dim3(Ln / GB_N, 2, Bn), 128>>>(
        f_c2_w, p_bufB, f_c2_b, p_x1, out, Cn, HID);
}